// round 3
// baseline (speedup 1.0000x reference)
#include <cuda_runtime.h>
#include <math.h>
#include <stdint.h>

// Problem constants (fixed shapes for this problem instance)
#define DIMX  4096
#define NT    4096      // total tokens B*S
#define NH    32
#define NKV   8
#define HDIM  128
#define BB    2
#define SEQ   2048
#define WIN   1024

// Scratch (device globals: allocation-free rule)
__device__ float g_q [(size_t)NT * NH  * HDIM];   // 64 MB
__device__ float g_k [(size_t)NT * NKV * HDIM];   // 16 MB
__device__ float g_v [(size_t)NT * NKV * HDIM];   // 16 MB
__device__ float g_ao[(size_t)NT * NH  * HDIM];   // 64 MB

// ---------------------------------------------------------------------------
// SGEMM: C[M,N] = A[M,K] @ B[K,N], all row-major. 128x128x16 tile, 8x8/thread.
// ---------------------------------------------------------------------------
#define BM 128
#define BN 128
#define BKT 16

__device__ __forceinline__ void sgemm_body(
    const float* __restrict__ A, int lda,
    const float* __restrict__ Bp, int ldb,
    float* __restrict__ C, int ldc,
    int K, int m0)
{
    __shared__ float As[BKT][BM];
    __shared__ float Bs[BKT][BN];

    const int tid = threadIdx.x;
    const int ty = tid >> 4;      // 0..15 -> m sub-tile
    const int tx = tid & 15;      // 0..15 -> n sub-tile

    float acc[8][8];
#pragma unroll
    for (int i = 0; i < 8; i++)
#pragma unroll
        for (int j = 0; j < 8; j++) acc[i][j] = 0.0f;

    const int a_row = tid >> 2;          // 0..63
    const int a_c4  = (tid & 3) << 2;    // 0,4,8,12
    const int b_row = tid >> 5;          // 0..7
    const int b_c4  = (tid & 31) << 2;   // 0..124

    const float* Abase = A + (size_t)m0 * lda;

    for (int kt = 0; kt < K; kt += BKT) {
        // Load A tile (128 x 16), store transposed into As[k][m]
#pragma unroll
        for (int it = 0; it < 2; it++) {
            int r = a_row + it * 64;
            float4 av = *reinterpret_cast<const float4*>(
                Abase + (size_t)r * lda + kt + a_c4);
            As[a_c4 + 0][r] = av.x;
            As[a_c4 + 1][r] = av.y;
            As[a_c4 + 2][r] = av.z;
            As[a_c4 + 3][r] = av.w;
        }
        // Load B tile (16 x 128)
#pragma unroll
        for (int it = 0; it < 2; it++) {
            int r = b_row + it * 8;
            *reinterpret_cast<float4*>(&Bs[r][b_c4]) =
                *reinterpret_cast<const float4*>(
                    Bp + (size_t)(kt + r) * ldb + b_c4);
        }
        __syncthreads();

#pragma unroll
        for (int k = 0; k < BKT; k++) {
            float af[8], bf[8];
            *reinterpret_cast<float4*>(af)     = *reinterpret_cast<float4*>(&As[k][ty * 8]);
            *reinterpret_cast<float4*>(af + 4) = *reinterpret_cast<float4*>(&As[k][ty * 8 + 4]);
            *reinterpret_cast<float4*>(bf)     = *reinterpret_cast<float4*>(&Bs[k][tx * 8]);
            *reinterpret_cast<float4*>(bf + 4) = *reinterpret_cast<float4*>(&Bs[k][tx * 8 + 4]);
#pragma unroll
            for (int i = 0; i < 8; i++)
#pragma unroll
                for (int j = 0; j < 8; j++)
                    acc[i][j] = fmaf(af[i], bf[j], acc[i][j]);
        }
        __syncthreads();
    }

#pragma unroll
    for (int i = 0; i < 8; i++) {
        float* cp = C + (size_t)(m0 + ty * 8 + i) * ldc + tx * 8;
        float4 v0 = make_float4(acc[i][0], acc[i][1], acc[i][2], acc[i][3]);
        float4 v1 = make_float4(acc[i][4], acc[i][5], acc[i][6], acc[i][7]);
        *reinterpret_cast<float4*>(cp)     = v0;
        *reinterpret_cast<float4*>(cp + 4) = v1;
    }
}

// Fused QKV projection: one grid, column blocks 0..31 -> Q, 32..39 -> K, 40..47 -> V
__global__ __launch_bounds__(256, 2)
void qkv_kernel(const float* __restrict__ x,
                const float* __restrict__ wq,
                const float* __restrict__ wk,
                const float* __restrict__ wv)
{
    int bn = blockIdx.x;
    int m0 = blockIdx.y * BM;
    const float* Bp;
    float* C;
    int ld;
    if (bn < 32)      { Bp = wq + bn * BN;        C = g_q + bn * BN;        ld = NH  * HDIM; }
    else if (bn < 40) { Bp = wk + (bn - 32) * BN; C = g_k + (bn - 32) * BN; ld = NKV * HDIM; }
    else              { Bp = wv + (bn - 40) * BN; C = g_v + (bn - 40) * BN; ld = NKV * HDIM; }
    sgemm_body(x, DIMX, Bp, ld, C, ld, DIMX, m0);
}

// Output projection: d_out = g_ao @ wo
__global__ __launch_bounds__(256, 2)
void out_gemm_kernel(const float* __restrict__ wo, float* __restrict__ out)
{
    sgemm_body(g_ao, NH * HDIM,
               wo + blockIdx.x * BN, DIMX,
               out + blockIdx.x * BN, DIMX,
               NH * HDIM, blockIdx.y * BM);
}

// ---------------------------------------------------------------------------
// RoPE (interleaved pairs) applied in place to g_q and g_k.
// ---------------------------------------------------------------------------
__global__ void rope_kernel(const float* __restrict__ cosb,
                            const float* __restrict__ sinb)
{
    int idx = blockIdx.x * blockDim.x + threadIdx.x;
    const int total = NT * (NH + NKV) * (HDIM / 2);
    if (idx >= total) return;
    int m    = idx & 63;                 // pair index 0..63
    int rest = idx >> 6;
    int head = rest % (NH + NKV);
    int t    = rest / (NH + NKV);
    float c = cosb[t * 64 + m];
    float s = sinb[t * 64 + m];
    float* base;
    if (head < NH) base = g_q + ((size_t)t * NH + head) * HDIM;
    else           base = g_k + ((size_t)t * NKV + (head - NH)) * HDIM;
    float t0 = base[2 * m];
    float t1 = base[2 * m + 1];
    base[2 * m]     = t0 * c - t1 * s;
    base[2 * m + 1] = t0 * s + t1 * c;
}

// ---------------------------------------------------------------------------
// Flash attention, sliding window, GQA. 1 CTA per (qtile=64, head, batch).
// ---------------------------------------------------------------------------
#define BQ 64
#define KPAD 132   // row stride for Qs/Ks/Vs (floats), 16B-aligned, conflict-reduced
#define PPAD 68    // row stride for Ps

#define ATTN_SMEM ((3 * 64 * KPAD + 64 * PPAD) * 4)

__global__ __launch_bounds__(256, 1)
void attn_kernel()
{
    extern __shared__ float sm[];
    float* Qs = sm;                    // [64][KPAD]
    float* Ks = Qs + 64 * KPAD;        // [64][KPAD]
    float* Vs = Ks + 64 * KPAD;        // [64][KPAD]
    float* Ps = Vs + 64 * KPAD;        // [64][PPAD]

    const int q0  = blockIdx.x * BQ;
    const int h   = blockIdx.y;
    const int b   = blockIdx.z;
    const int kvh = h >> 2;            // GQA: 4 q-heads per kv-head
    const int tid = threadIdx.x;
    const int ty  = tid >> 4;          // 0..15 (q rows ty*4..ty*4+3)
    const int tx  = tid & 15;          // 0..15

    const float scale = 0.08838834764831845f;  // 1/sqrt(128)

    // Load Q tile, pre-scaled
    const float* qbase = g_q + ((size_t)(b * SEQ + q0) * NH + h) * HDIM;
#pragma unroll
    for (int it = 0; it < 8; it++) {
        int i = tid + it * 256;
        int r = i >> 5;
        int c4 = (i & 31) << 2;
        float4 v = *reinterpret_cast<const float4*>(qbase + (size_t)r * (NH * HDIM) + c4);
        v.x *= scale; v.y *= scale; v.z *= scale; v.w *= scale;
        *reinterpret_cast<float4*>(&Qs[r * KPAD + c4]) = v;
    }

    float m_run[4], l_run[4], o[4][8];
#pragma unroll
    for (int ii = 0; ii < 4; ii++) {
        m_run[ii] = -INFINITY;
        l_run[ii] = 0.0f;
#pragma unroll
        for (int cc = 0; cc < 8; cc++) o[ii][cc] = 0.0f;
    }

    int jlo = q0 - (WIN - 1);
    if (jlo < 0) jlo = 0;
    const int tk0 = jlo >> 6;
    const int tk1 = q0 >> 6;

    const float* kbase = g_k + ((size_t)(b * SEQ) * NKV + kvh) * HDIM;
    const float* vbase = g_v + ((size_t)(b * SEQ) * NKV + kvh) * HDIM;

    for (int tk = tk0; tk <= tk1; tk++) {
        const int j0 = tk * 64;
        __syncthreads();   // protect Ks/Vs/Ps from previous iteration readers

        // Load K & V tiles (64 x 128 each)
#pragma unroll
        for (int it = 0; it < 8; it++) {
            int i = tid + it * 256;
            int r = i >> 5;
            int c4 = (i & 31) << 2;
            size_t goff = (size_t)(j0 + r) * (NKV * HDIM) + c4;
            *reinterpret_cast<float4*>(&Ks[r * KPAD + c4]) =
                *reinterpret_cast<const float4*>(kbase + goff);
            *reinterpret_cast<float4*>(&Vs[r * KPAD + c4]) =
                *reinterpret_cast<const float4*>(vbase + goff);
        }
        __syncthreads();

        // Scores: thread owns q rows ty*4+ii, key cols j0 + tx + 16*jj
        float s[4][4];
#pragma unroll
        for (int ii = 0; ii < 4; ii++)
#pragma unroll
            for (int jj = 0; jj < 4; jj++) s[ii][jj] = 0.0f;

#pragma unroll 4
        for (int d4 = 0; d4 < 32; d4++) {
            float4 qv[4], kv[4];
#pragma unroll
            for (int ii = 0; ii < 4; ii++)
                qv[ii] = *reinterpret_cast<float4*>(&Qs[(ty * 4 + ii) * KPAD + d4 * 4]);
#pragma unroll
            for (int jj = 0; jj < 4; jj++)
                kv[jj] = *reinterpret_cast<float4*>(&Ks[(tx + 16 * jj) * KPAD + d4 * 4]);
#pragma unroll
            for (int ii = 0; ii < 4; ii++)
#pragma unroll
                for (int jj = 0; jj < 4; jj++) {
                    s[ii][jj] = fmaf(qv[ii].x, kv[jj].x, s[ii][jj]);
                    s[ii][jj] = fmaf(qv[ii].y, kv[jj].y, s[ii][jj]);
                    s[ii][jj] = fmaf(qv[ii].z, kv[jj].z, s[ii][jj]);
                    s[ii][jj] = fmaf(qv[ii].w, kv[jj].w, s[ii][jj]);
                }
        }

        // Mask + online softmax update
#pragma unroll
        for (int ii = 0; ii < 4; ii++) {
            const int qi = q0 + ty * 4 + ii;
            float mx = -INFINITY;
            bool valid[4];
#pragma unroll
            for (int jj = 0; jj < 4; jj++) {
                const int kj = j0 + tx + 16 * jj;
                bool ok = (kj <= qi) && (qi - kj < WIN);
                valid[jj] = ok;
                if (ok) mx = fmaxf(mx, s[ii][jj]);
            }
#pragma unroll
            for (int off = 8; off >= 1; off >>= 1)
                mx = fmaxf(mx, __shfl_xor_sync(0xffffffffu, mx, off, 32));

            float mnew = fmaxf(m_run[ii], mx);
            float alpha = __expf(m_run[ii] - mnew);
            if (mnew == -INFINITY) alpha = 1.0f;   // fully-masked so far: avoid NaN

            float rsum = 0.0f;
#pragma unroll
            for (int jj = 0; jj < 4; jj++) {
                float p = valid[jj] ? __expf(s[ii][jj] - mnew) : 0.0f;
                Ps[(ty * 4 + ii) * PPAD + tx + 16 * jj] = p;
                rsum += p;
            }
#pragma unroll
            for (int off = 8; off >= 1; off >>= 1)
                rsum += __shfl_xor_sync(0xffffffffu, rsum, off, 32);

            l_run[ii] = l_run[ii] * alpha + rsum;
            m_run[ii] = mnew;
#pragma unroll
            for (int cc = 0; cc < 8; cc++) o[ii][cc] *= alpha;
        }
        __syncthreads();

        // PV: o[ii][cc] += P[row][j] * V[j][tx*8+cc]
#pragma unroll 2
        for (int j4 = 0; j4 < 16; j4++) {
            float pr[4][4];
#pragma unroll
            for (int ii = 0; ii < 4; ii++)
                *reinterpret_cast<float4*>(pr[ii]) =
                    *reinterpret_cast<float4*>(&Ps[(ty * 4 + ii) * PPAD + j4 * 4]);
#pragma unroll
            for (int jj = 0; jj < 4; jj++) {
                const int j = j4 * 4 + jj;
                float4 v0 = *reinterpret_cast<float4*>(&Vs[j * KPAD + tx * 8]);
                float4 v1 = *reinterpret_cast<float4*>(&Vs[j * KPAD + tx * 8 + 4]);
#pragma unroll
                for (int ii = 0; ii < 4; ii++) {
                    float p = pr[ii][jj];
                    o[ii][0] = fmaf(p, v0.x, o[ii][0]);
                    o[ii][1] = fmaf(p, v0.y, o[ii][1]);
                    o[ii][2] = fmaf(p, v0.z, o[ii][2]);
                    o[ii][3] = fmaf(p, v0.w, o[ii][3]);
                    o[ii][4] = fmaf(p, v1.x, o[ii][4]);
                    o[ii][5] = fmaf(p, v1.y, o[ii][5]);
                    o[ii][6] = fmaf(p, v1.z, o[ii][6]);
                    o[ii][7] = fmaf(p, v1.w, o[ii][7]);
                }
            }
        }
    }

    // Epilogue: normalize and store to g_ao[T][H*HD]
    float* obase = g_ao + (size_t)(b * SEQ + q0) * (NH * HDIM) + h * HDIM;
#pragma unroll
    for (int ii = 0; ii < 4; ii++) {
        float inv = 1.0f / l_run[ii];
        float4 v0 = make_float4(o[ii][0] * inv, o[ii][1] * inv, o[ii][2] * inv, o[ii][3] * inv);
        float4 v1 = make_float4(o[ii][4] * inv, o[ii][5] * inv, o[ii][6] * inv, o[ii][7] * inv);
        float* cp = obase + (size_t)(ty * 4 + ii) * (NH * HDIM) + tx * 8;
        *reinterpret_cast<float4*>(cp)     = v0;
        *reinterpret_cast<float4*>(cp + 4) = v1;
    }
}

// ---------------------------------------------------------------------------
extern "C" void kernel_launch(void* const* d_in, const int* in_sizes, int n_in,
                              void* d_out, int out_size)
{
    const float* x    = (const float*)d_in[0];
    const float* cosb = (const float*)d_in[1];
    const float* sinb = (const float*)d_in[2];
    const float* wq   = (const float*)d_in[3];
    const float* wk   = (const float*)d_in[4];
    const float* wv   = (const float*)d_in[5];
    const float* wo   = (const float*)d_in[6];
    float* out = (float*)d_out;

    cudaFuncSetAttribute(attn_kernel,
                         cudaFuncAttributeMaxDynamicSharedMemorySize, ATTN_SMEM);

    // 1. QKV projections (fused into one grid)
    qkv_kernel<<<dim3(48, 32), 256>>>(x, wq, wk, wv);

    // 2. RoPE on q and k
    {
        const int total = NT * (NH + NKV) * (HDIM / 2);
        rope_kernel<<<(total + 255) / 256, 256>>>(cosb, sinb);
    }

    // 3. Sliding-window GQA attention
    attn_kernel<<<dim3(SEQ / BQ, NH, BB), 256, ATTN_SMEM>>>();

    // 4. Output projection
    out_gemm_kernel<<<dim3(32, 32), 256>>>(wo, out);
}

// round 7
// speedup vs baseline: 2.6092x; 2.6092x over previous
#include <cuda_runtime.h>
#include <math.h>
#include <stdint.h>

// Problem constants
#define DIMX  4096
#define NT    4096      // total tokens B*S
#define NH    32
#define NKV   8
#define HDIM  128
#define BB    2
#define SEQ   2048
#define WIN   1024

// ---------------------------------------------------------------------------
// Scratch (device globals: allocation-free rule)
// ---------------------------------------------------------------------------
__device__ float g_q  [(size_t)NT * NH  * HDIM];   // 64 MB
__device__ float g_k  [(size_t)NT * NKV * HDIM];   // 16 MB
__device__ float g_v  [(size_t)NT * NKV * HDIM];   // 16 MB
__device__ float g_ao [(size_t)NT * NH  * HDIM];   // 64 MB

// ---------------------------------------------------------------------------
// PTX helpers (sm_80-compatible subset only: cp.async + mma.sync tf32)
// ---------------------------------------------------------------------------
#define CP_ASYNC16(dst, src) \
    asm volatile("cp.async.cg.shared.global [%0], [%1], 16;" :: "r"(dst), "l"(src))
#define CP_COMMIT() asm volatile("cp.async.commit_group;" ::: "memory")
#define CP_WAIT(n)  asm volatile("cp.async.wait_group %0;" :: "n"(n) : "memory")

__device__ __forceinline__ uint32_t smem_u32(const void* p) {
    uint32_t a;
    asm("{ .reg .u64 t; cvta.to.shared.u64 t, %1; cvt.u32.u64 %0, t; }" : "=r"(a) : "l"(p));
    return a;
}

__device__ __forceinline__ uint32_t tf32u(float x) {
    uint32_t u;
    asm("cvt.rn.tf32.f32 %0, %1;" : "=r"(u) : "f"(x));
    return u;
}

// D = A(16x8, tf32) * B(8x8, tf32) + C, fp32 accum, in-place on acc
__device__ __forceinline__ void mma_tf32(float* acc, const uint32_t* a, const uint32_t* b)
{
    asm volatile(
        "mma.sync.aligned.m16n8k8.row.col.f32.tf32.tf32.f32 "
        "{%0,%1,%2,%3}, {%4,%5,%6,%7}, {%8,%9}, {%0,%1,%2,%3};"
        : "+f"(acc[0]), "+f"(acc[1]), "+f"(acc[2]), "+f"(acc[3])
        : "r"(a[0]), "r"(a[1]), "r"(a[2]), "r"(a[3]), "r"(b[0]), "r"(b[1]));
}

// ---------------------------------------------------------------------------
// Tensor-core tf32 GEMM: C[128,128] tile of A[M,4096] @ B[4096,N].
// 256 threads = 8 warps (2x4 warp grid, 64x32 per warp), BK=32, 3-stage cp.async.
// Operands RN-rounded to tf32 in-register => no pre-passes, no transposes.
// ---------------------------------------------------------------------------
#define BK    32
#define AST   36    // As row stride (floats): banks (4*g + t) all distinct
#define BST   136   // Bs row stride (floats): banks (8*t + g) all distinct
#define NSTG  3
#define AS_FLOATS (128 * AST)            // 4608
#define BS_FLOATS (BK * BST)             // 4352
#define GEMM_SMEM ((NSTG * (AS_FLOATS + BS_FLOATS)) * 4)   // 107,520 B
#define NITER (DIMX / BK)                // 128

__device__ __forceinline__ void g_load_stage(
    uint32_t sa, uint32_t sb,
    const float* __restrict__ A,     // pre-offset to row m0, lda = 4096
    const float* __restrict__ B,     // pre-offset to col n0
    int ldb, int kt, int tid)
{
    const float* ab = A + kt;
#pragma unroll
    for (int j = 0; j < 4; j++) {
        int c = tid + j * 256;
        int r = c >> 3, w = c & 7;                    // 128 rows x 8 chunks
        CP_ASYNC16(sa + (uint32_t)(r * AST + w * 4) * 4,
                   ab + (size_t)r * DIMX + w * 4);
    }
    const float* bb = B + (size_t)kt * ldb;
#pragma unroll
    for (int j = 0; j < 4; j++) {
        int c = tid + j * 256;
        int r = c >> 5, w = c & 31;                   // 32 rows x 32 chunks
        CP_ASYNC16(sb + (uint32_t)(r * BST + w * 4) * 4,
                   bb + (size_t)r * ldb + w * 4);
    }
}

__device__ __forceinline__ void tc_gemm_body(
    const float* __restrict__ A,     // [M,4096] row-major, pre-offset to m0
    const float* __restrict__ B,     // [4096,N] row-major, pre-offset to n0
    float* __restrict__ C,           // pre-offset to n0
    int ldb, int ldc)
{
    extern __shared__ float sh[];
    float* As = sh;                          // [NSTG][128][AST]
    float* Bs = sh + NSTG * AS_FLOATS;       // [NSTG][BK][BST]
    const uint32_t sa0 = smem_u32(As);
    const uint32_t sb0 = smem_u32(Bs);

    const int tid  = threadIdx.x;
    const int wid  = tid >> 5;
    const int lane = tid & 31;
    const int wm   = (wid >> 2) * 64;        // warp M offset (0/64)
    const int wn   = (wid & 3) * 32;         // warp N offset (0..96)
    const int gid  = lane >> 2;              // 0..7
    const int tig  = lane & 3;               // 0..3

    float acc[4][4][4];
#pragma unroll
    for (int mt = 0; mt < 4; mt++)
#pragma unroll
        for (int nt = 0; nt < 4; nt++)
#pragma unroll
            for (int q = 0; q < 4; q++) acc[mt][nt][q] = 0.0f;

    // Prologue: stages 0,1
#pragma unroll
    for (int p = 0; p < NSTG - 1; p++) {
        g_load_stage(sa0 + (uint32_t)p * AS_FLOATS * 4,
                     sb0 + (uint32_t)p * BS_FLOATS * 4,
                     A, B, ldb, p * BK, tid);
        CP_COMMIT();
    }

    for (int i = 0; i < NITER; i++) {
        CP_WAIT(NSTG - 2);
        __syncthreads();
        const int s = i % NSTG;
        const float* Asb = As + s * AS_FLOATS + wm * AST;
        const float* Bsb = Bs + s * BS_FLOATS + wn;

#pragma unroll
        for (int ks = 0; ks < 4; ks++) {
            const int k0 = ks * 8;
            uint32_t af[4][4], bf[4][2];
#pragma unroll
            for (int mt = 0; mt < 4; mt++) {
                const float* ap = Asb + (mt * 16 + gid) * AST + k0 + tig;
                af[mt][0] = tf32u(ap[0]);
                af[mt][1] = tf32u(ap[8 * AST]);
                af[mt][2] = tf32u(ap[4]);
                af[mt][3] = tf32u(ap[8 * AST + 4]);
            }
#pragma unroll
            for (int nt = 0; nt < 4; nt++) {
                const float* bp = Bsb + (k0 + tig) * BST + nt * 8 + gid;
                bf[nt][0] = tf32u(bp[0]);
                bf[nt][1] = tf32u(bp[4 * BST]);
            }
#pragma unroll
            for (int mt = 0; mt < 4; mt++)
#pragma unroll
                for (int nt = 0; nt < 4; nt++)
                    mma_tf32(acc[mt][nt], af[mt], bf[nt]);
        }

        const int ip = i + NSTG - 1;
        if (ip < NITER) {
            const int sp = ip % NSTG;
            g_load_stage(sa0 + (uint32_t)sp * AS_FLOATS * 4,
                         sb0 + (uint32_t)sp * BS_FLOATS * 4,
                         A, B, ldb, ip * BK, tid);
        }
        CP_COMMIT();
    }

    // Epilogue: c0/c1 at (row, 2*tig), c2/c3 at (row+8, 2*tig)
#pragma unroll
    for (int mt = 0; mt < 4; mt++) {
#pragma unroll
        for (int nt = 0; nt < 4; nt++) {
            const int r0 = wm + mt * 16 + gid;
            const int cc = wn + nt * 8 + tig * 2;
            float2 v0 = make_float2(acc[mt][nt][0], acc[mt][nt][1]);
            float2 v1 = make_float2(acc[mt][nt][2], acc[mt][nt][3]);
            *reinterpret_cast<float2*>(C + (size_t)r0 * ldc + cc)       = v0;
            *reinterpret_cast<float2*>(C + (size_t)(r0 + 8) * ldc + cc) = v1;
        }
    }
}

// Fused QKV: column blocks 0..31 -> Q, 32..39 -> K, 40..47 -> V
__global__ __launch_bounds__(256, 1)
void qkv_tc_kernel(const float* __restrict__ x,
                   const float* __restrict__ wq,
                   const float* __restrict__ wk,
                   const float* __restrict__ wv)
{
    const int bn = blockIdx.x;
    const int m0 = blockIdx.y * 128;
    const float* Bp; float* C; int ldb;
    if (bn < 32)      { Bp = wq + bn * 128;        C = g_q + bn * 128;        ldb = NH  * HDIM; }
    else if (bn < 40) { Bp = wk + (bn - 32) * 128; C = g_k + (bn - 32) * 128; ldb = NKV * HDIM; }
    else              { Bp = wv + (bn - 40) * 128; C = g_v + (bn - 40) * 128; ldb = NKV * HDIM; }
    tc_gemm_body(x + (size_t)m0 * DIMX, Bp, C + (size_t)m0 * ldb, ldb, ldb);
}

__global__ __launch_bounds__(256, 1)
void out_tc_kernel(const float* __restrict__ wo, float* __restrict__ out)
{
    const int n0 = blockIdx.x * 128;
    const int m0 = blockIdx.y * 128;
    tc_gemm_body(g_ao + (size_t)m0 * DIMX, wo + n0,
                 out + (size_t)m0 * DIMX + n0, DIMX, DIMX);
}

// ---------------------------------------------------------------------------
// RoPE (interleaved pairs), in place on g_q / g_k
// ---------------------------------------------------------------------------
__global__ void rope_kernel(const float* __restrict__ cosb,
                            const float* __restrict__ sinb)
{
    int idx = blockIdx.x * blockDim.x + threadIdx.x;
    const int total = NT * (NH + NKV) * (HDIM / 2);
    if (idx >= total) return;
    int m    = idx & 63;
    int rest = idx >> 6;
    int head = rest % (NH + NKV);
    int t    = rest / (NH + NKV);
    float c = cosb[t * 64 + m];
    float s = sinb[t * 64 + m];
    float* base;
    if (head < NH) base = g_q + ((size_t)t * NH + head) * HDIM;
    else           base = g_k + ((size_t)t * NKV + (head - NH)) * HDIM;
    float t0 = base[2 * m];
    float t1 = base[2 * m + 1];
    base[2 * m]     = t0 * c - t1 * s;
    base[2 * m + 1] = t0 * s + t1 * c;
}

// ---------------------------------------------------------------------------
// Flash attention, sliding window, GQA (fp32 FFMA)
// ---------------------------------------------------------------------------
#define BQ 64
#define KPAD 132
#define PPAD 68
#define ATTN_SMEM ((3 * 64 * KPAD + 64 * PPAD) * 4)

__global__ __launch_bounds__(256, 1)
void attn_kernel()
{
    extern __shared__ float sm[];
    float* Qs = sm;
    float* Ks = Qs + 64 * KPAD;
    float* Vs = Ks + 64 * KPAD;
    float* Ps = Vs + 64 * KPAD;

    const int q0  = blockIdx.x * BQ;
    const int h   = blockIdx.y;
    const int b   = blockIdx.z;
    const int kvh = h >> 2;
    const int tid = threadIdx.x;
    const int ty  = tid >> 4;
    const int tx  = tid & 15;

    const float scale = 0.08838834764831845f;

    const float* qbase = g_q + ((size_t)(b * SEQ + q0) * NH + h) * HDIM;
#pragma unroll
    for (int it = 0; it < 8; it++) {
        int i = tid + it * 256;
        int r = i >> 5;
        int c4 = (i & 31) << 2;
        float4 v = *reinterpret_cast<const float4*>(qbase + (size_t)r * (NH * HDIM) + c4);
        v.x *= scale; v.y *= scale; v.z *= scale; v.w *= scale;
        *reinterpret_cast<float4*>(&Qs[r * KPAD + c4]) = v;
    }

    float m_run[4], l_run[4], o[4][8];
#pragma unroll
    for (int ii = 0; ii < 4; ii++) {
        m_run[ii] = -INFINITY;
        l_run[ii] = 0.0f;
#pragma unroll
        for (int cc = 0; cc < 8; cc++) o[ii][cc] = 0.0f;
    }

    int jlo = q0 - (WIN - 1);
    if (jlo < 0) jlo = 0;
    const int tk0 = jlo >> 6;
    const int tk1 = q0 >> 6;

    const float* kbase = g_k + ((size_t)(b * SEQ) * NKV + kvh) * HDIM;
    const float* vbase = g_v + ((size_t)(b * SEQ) * NKV + kvh) * HDIM;

    for (int tk = tk0; tk <= tk1; tk++) {
        const int j0 = tk * 64;
        __syncthreads();

#pragma unroll
        for (int it = 0; it < 8; it++) {
            int i = tid + it * 256;
            int r = i >> 5;
            int c4 = (i & 31) << 2;
            size_t goff = (size_t)(j0 + r) * (NKV * HDIM) + c4;
            *reinterpret_cast<float4*>(&Ks[r * KPAD + c4]) =
                *reinterpret_cast<const float4*>(kbase + goff);
            *reinterpret_cast<float4*>(&Vs[r * KPAD + c4]) =
                *reinterpret_cast<const float4*>(vbase + goff);
        }
        __syncthreads();

        float s[4][4];
#pragma unroll
        for (int ii = 0; ii < 4; ii++)
#pragma unroll
            for (int jj = 0; jj < 4; jj++) s[ii][jj] = 0.0f;

#pragma unroll 4
        for (int d4 = 0; d4 < 32; d4++) {
            float4 qv[4], kv[4];
#pragma unroll
            for (int ii = 0; ii < 4; ii++)
                qv[ii] = *reinterpret_cast<float4*>(&Qs[(ty * 4 + ii) * KPAD + d4 * 4]);
#pragma unroll
            for (int jj = 0; jj < 4; jj++)
                kv[jj] = *reinterpret_cast<float4*>(&Ks[(tx + 16 * jj) * KPAD + d4 * 4]);
#pragma unroll
            for (int ii = 0; ii < 4; ii++)
#pragma unroll
                for (int jj = 0; jj < 4; jj++) {
                    s[ii][jj] = fmaf(qv[ii].x, kv[jj].x, s[ii][jj]);
                    s[ii][jj] = fmaf(qv[ii].y, kv[jj].y, s[ii][jj]);
                    s[ii][jj] = fmaf(qv[ii].z, kv[jj].z, s[ii][jj]);
                    s[ii][jj] = fmaf(qv[ii].w, kv[jj].w, s[ii][jj]);
                }
        }

#pragma unroll
        for (int ii = 0; ii < 4; ii++) {
            const int qi = q0 + ty * 4 + ii;
            float mx = -INFINITY;
            bool valid[4];
#pragma unroll
            for (int jj = 0; jj < 4; jj++) {
                const int kj = j0 + tx + 16 * jj;
                bool ok = (kj <= qi) && (qi - kj < WIN);
                valid[jj] = ok;
                if (ok) mx = fmaxf(mx, s[ii][jj]);
            }
#pragma unroll
            for (int off = 8; off >= 1; off >>= 1)
                mx = fmaxf(mx, __shfl_xor_sync(0xffffffffu, mx, off, 32));

            float mnew = fmaxf(m_run[ii], mx);
            float alpha = __expf(m_run[ii] - mnew);
            if (mnew == -INFINITY) alpha = 1.0f;

            float rsum = 0.0f;
#pragma unroll
            for (int jj = 0; jj < 4; jj++) {
                float p = valid[jj] ? __expf(s[ii][jj] - mnew) : 0.0f;
                Ps[(ty * 4 + ii) * PPAD + tx + 16 * jj] = p;
                rsum += p;
            }
#pragma unroll
            for (int off = 8; off >= 1; off >>= 1)
                rsum += __shfl_xor_sync(0xffffffffu, rsum, off, 32);

            l_run[ii] = l_run[ii] * alpha + rsum;
            m_run[ii] = mnew;
#pragma unroll
            for (int cc = 0; cc < 8; cc++) o[ii][cc] *= alpha;
        }
        __syncthreads();

#pragma unroll 2
        for (int j4 = 0; j4 < 16; j4++) {
            float pr[4][4];
#pragma unroll
            for (int ii = 0; ii < 4; ii++)
                *reinterpret_cast<float4*>(pr[ii]) =
                    *reinterpret_cast<float4*>(&Ps[(ty * 4 + ii) * PPAD + j4 * 4]);
#pragma unroll
            for (int jj = 0; jj < 4; jj++) {
                const int j = j4 * 4 + jj;
                float4 v0 = *reinterpret_cast<float4*>(&Vs[j * KPAD + tx * 8]);
                float4 v1 = *reinterpret_cast<float4*>(&Vs[j * KPAD + tx * 8 + 4]);
#pragma unroll
                for (int ii = 0; ii < 4; ii++) {
                    float p = pr[ii][jj];
                    o[ii][0] = fmaf(p, v0.x, o[ii][0]);
                    o[ii][1] = fmaf(p, v0.y, o[ii][1]);
                    o[ii][2] = fmaf(p, v0.z, o[ii][2]);
                    o[ii][3] = fmaf(p, v0.w, o[ii][3]);
                    o[ii][4] = fmaf(p, v1.x, o[ii][4]);
                    o[ii][5] = fmaf(p, v1.y, o[ii][5]);
                    o[ii][6] = fmaf(p, v1.z, o[ii][6]);
                    o[ii][7] = fmaf(p, v1.w, o[ii][7]);
                }
            }
        }
    }

    float* obase = g_ao + (size_t)(b * SEQ + q0) * (NH * HDIM) + h * HDIM;
#pragma unroll
    for (int ii = 0; ii < 4; ii++) {
        float inv = 1.0f / l_run[ii];
        float4 v0 = make_float4(o[ii][0] * inv, o[ii][1] * inv, o[ii][2] * inv, o[ii][3] * inv);
        float4 v1 = make_float4(o[ii][4] * inv, o[ii][5] * inv, o[ii][6] * inv, o[ii][7] * inv);
        float* cp = obase + (size_t)(ty * 4 + ii) * (NH * HDIM) + tx * 8;
        *reinterpret_cast<float4*>(cp)     = v0;
        *reinterpret_cast<float4*>(cp + 4) = v1;
    }
}

// ---------------------------------------------------------------------------
extern "C" void kernel_launch(void* const* d_in, const int* in_sizes, int n_in,
                              void* d_out, int out_size)
{
    const float* x    = (const float*)d_in[0];
    const float* cosb = (const float*)d_in[1];
    const float* sinb = (const float*)d_in[2];
    const float* wq   = (const float*)d_in[3];
    const float* wk   = (const float*)d_in[4];
    const float* wv   = (const float*)d_in[5];
    const float* wo   = (const float*)d_in[6];
    float* out = (float*)d_out;

    cudaFuncSetAttribute(attn_kernel,
                         cudaFuncAttributeMaxDynamicSharedMemorySize, ATTN_SMEM);
    cudaFuncSetAttribute(qkv_tc_kernel,
                         cudaFuncAttributeMaxDynamicSharedMemorySize, GEMM_SMEM);
    cudaFuncSetAttribute(out_tc_kernel,
                         cudaFuncAttributeMaxDynamicSharedMemorySize, GEMM_SMEM);

    // 1. QKV projections (mma.sync tf32, fused grid)
    qkv_tc_kernel<<<dim3(48, 32), 256, GEMM_SMEM>>>(x, wq, wk, wv);

    // 2. RoPE
    {
        const int total = NT * (NH + NKV) * (HDIM / 2);
        rope_kernel<<<(total + 255) / 256, 256>>>(cosb, sinb);
    }

    // 3. Sliding-window GQA attention
    attn_kernel<<<dim3(SEQ / BQ, NH, BB), 256, ATTN_SMEM>>>();

    // 4. Output projection (mma.sync tf32)
    out_tc_kernel<<<dim3(32, 32), 256, GEMM_SMEM>>>(wo, out);
}

// round 9
// speedup vs baseline: 2.6122x; 1.0012x over previous
#include <cuda_runtime.h>
#include <math.h>
#include <stdint.h>

// Problem constants
#define DIMX  4096
#define NT    4096      // total tokens B*S
#define NH    32
#define NKV   8
#define HDIM  128
#define BB    2
#define SEQ   2048
#define WIN   1024

// ---------------------------------------------------------------------------
// Scratch (device globals: allocation-free rule)
// ---------------------------------------------------------------------------
__device__ float g_q  [(size_t)NT * NH  * HDIM];   // 64 MB
__device__ float g_k  [(size_t)NT * NKV * HDIM];   // 16 MB
__device__ float g_v  [(size_t)NT * NKV * HDIM];   // 16 MB
__device__ float g_ao [(size_t)NT * NH  * HDIM];   // 64 MB

// ---------------------------------------------------------------------------
// PTX helpers (sm_80-compatible subset only: cp.async + mma.sync tf32)
// ---------------------------------------------------------------------------
#define CP_ASYNC16(dst, src) \
    asm volatile("cp.async.cg.shared.global [%0], [%1], 16;" :: "r"(dst), "l"(src))
#define CP_COMMIT() asm volatile("cp.async.commit_group;" ::: "memory")
#define CP_WAIT(n)  asm volatile("cp.async.wait_group %0;" :: "n"(n) : "memory")

__device__ __forceinline__ uint32_t smem_u32(const void* p) {
    uint32_t a;
    asm("{ .reg .u64 t; cvta.to.shared.u64 t, %1; cvt.u32.u64 %0, t; }" : "=r"(a) : "l"(p));
    return a;
}

__device__ __forceinline__ uint32_t tf32u(float x) {
    uint32_t u;
    asm("cvt.rn.tf32.f32 %0, %1;" : "=r"(u) : "f"(x));
    return u;
}

// D = A(16x8, tf32) * B(8x8, tf32) + C, fp32 accum, in-place on acc
__device__ __forceinline__ void mma_tf32(float* acc, const uint32_t* a, const uint32_t* b)
{
    asm volatile(
        "mma.sync.aligned.m16n8k8.row.col.f32.tf32.tf32.f32 "
        "{%0,%1,%2,%3}, {%4,%5,%6,%7}, {%8,%9}, {%0,%1,%2,%3};"
        : "+f"(acc[0]), "+f"(acc[1]), "+f"(acc[2]), "+f"(acc[3])
        : "r"(a[0]), "r"(a[1]), "r"(a[2]), "r"(a[3]), "r"(b[0]), "r"(b[1]));
}

// ---------------------------------------------------------------------------
// Tensor-core tf32 GEMM: C[128,128] tile of A[M,4096] @ B[4096,N].
// 256 threads = 8 warps (2x4 warp grid, 64x32 per warp), BK=32, 3-stage cp.async.
// Operands RN-rounded to tf32 in-register => no pre-passes, no transposes.
// ---------------------------------------------------------------------------
#define BK    32
#define AST   36    // As row stride (floats): banks (4*g + t) all distinct
#define BST   136   // Bs row stride (floats): banks (8*t + g) all distinct
#define NSTG  3
#define AS_FLOATS (128 * AST)            // 4608
#define BS_FLOATS (BK * BST)             // 4352
#define GEMM_SMEM ((NSTG * (AS_FLOATS + BS_FLOATS)) * 4)   // 107,520 B
#define NITER (DIMX / BK)                // 128

__device__ __forceinline__ void g_load_stage(
    uint32_t sa, uint32_t sb,
    const float* __restrict__ A,     // pre-offset to row m0, lda = 4096
    const float* __restrict__ B,     // pre-offset to col n0
    int ldb, int kt, int tid)
{
    const float* ab = A + kt;
#pragma unroll
    for (int j = 0; j < 4; j++) {
        int c = tid + j * 256;
        int r = c >> 3, w = c & 7;                    // 128 rows x 8 chunks
        CP_ASYNC16(sa + (uint32_t)(r * AST + w * 4) * 4,
                   ab + (size_t)r * DIMX + w * 4);
    }
    const float* bb = B + (size_t)kt * ldb;
#pragma unroll
    for (int j = 0; j < 4; j++) {
        int c = tid + j * 256;
        int r = c >> 5, w = c & 31;                   // 32 rows x 32 chunks
        CP_ASYNC16(sb + (uint32_t)(r * BST + w * 4) * 4,
                   bb + (size_t)r * ldb + w * 4);
    }
}

__device__ __forceinline__ void tc_gemm_body(
    const float* __restrict__ A,     // [M,4096] row-major, pre-offset to m0
    const float* __restrict__ B,     // [4096,N] row-major, pre-offset to n0
    float* __restrict__ C,           // pre-offset to n0
    int ldb, int ldc)
{
    extern __shared__ float sh[];
    float* As = sh;                          // [NSTG][128][AST]
    float* Bs = sh + NSTG * AS_FLOATS;       // [NSTG][BK][BST]
    const uint32_t sa0 = smem_u32(As);
    const uint32_t sb0 = smem_u32(Bs);

    const int tid  = threadIdx.x;
    const int wid  = tid >> 5;
    const int lane = tid & 31;
    const int wm   = (wid >> 2) * 64;        // warp M offset (0/64)
    const int wn   = (wid & 3) * 32;         // warp N offset (0..96)
    const int gid  = lane >> 2;              // 0..7
    const int tig  = lane & 3;               // 0..3

    float acc[4][4][4];
#pragma unroll
    for (int mt = 0; mt < 4; mt++)
#pragma unroll
        for (int nt = 0; nt < 4; nt++)
#pragma unroll
            for (int q = 0; q < 4; q++) acc[mt][nt][q] = 0.0f;

    // Prologue: stages 0,1
#pragma unroll
    for (int p = 0; p < NSTG - 1; p++) {
        g_load_stage(sa0 + (uint32_t)p * AS_FLOATS * 4,
                     sb0 + (uint32_t)p * BS_FLOATS * 4,
                     A, B, ldb, p * BK, tid);
        CP_COMMIT();
    }

    for (int i = 0; i < NITER; i++) {
        CP_WAIT(NSTG - 2);
        __syncthreads();
        const int s = i % NSTG;
        const float* Asb = As + s * AS_FLOATS + wm * AST;
        const float* Bsb = Bs + s * BS_FLOATS + wn;

#pragma unroll
        for (int ks = 0; ks < 4; ks++) {
            const int k0 = ks * 8;
            uint32_t af[4][4], bf[4][2];
#pragma unroll
            for (int mt = 0; mt < 4; mt++) {
                const float* ap = Asb + (mt * 16 + gid) * AST + k0 + tig;
                af[mt][0] = tf32u(ap[0]);
                af[mt][1] = tf32u(ap[8 * AST]);
                af[mt][2] = tf32u(ap[4]);
                af[mt][3] = tf32u(ap[8 * AST + 4]);
            }
#pragma unroll
            for (int nt = 0; nt < 4; nt++) {
                const float* bp = Bsb + (k0 + tig) * BST + nt * 8 + gid;
                bf[nt][0] = tf32u(bp[0]);
                bf[nt][1] = tf32u(bp[4 * BST]);
            }
#pragma unroll
            for (int mt = 0; mt < 4; mt++)
#pragma unroll
                for (int nt = 0; nt < 4; nt++)
                    mma_tf32(acc[mt][nt], af[mt], bf[nt]);
        }

        const int ip = i + NSTG - 1;
        if (ip < NITER) {
            const int sp = ip % NSTG;
            g_load_stage(sa0 + (uint32_t)sp * AS_FLOATS * 4,
                         sb0 + (uint32_t)sp * BS_FLOATS * 4,
                         A, B, ldb, ip * BK, tid);
        }
        CP_COMMIT();
    }

    // Epilogue: c0/c1 at (row, 2*tig), c2/c3 at (row+8, 2*tig)
#pragma unroll
    for (int mt = 0; mt < 4; mt++) {
#pragma unroll
        for (int nt = 0; nt < 4; nt++) {
            const int r0 = wm + mt * 16 + gid;
            const int cc = wn + nt * 8 + tig * 2;
            float2 v0 = make_float2(acc[mt][nt][0], acc[mt][nt][1]);
            float2 v1 = make_float2(acc[mt][nt][2], acc[mt][nt][3]);
            *reinterpret_cast<float2*>(C + (size_t)r0 * ldc + cc)       = v0;
            *reinterpret_cast<float2*>(C + (size_t)(r0 + 8) * ldc + cc) = v1;
        }
    }
}

// Fused QKV: column blocks 0..31 -> Q, 32..39 -> K, 40..47 -> V
__global__ __launch_bounds__(256, 1)
void qkv_tc_kernel(const float* __restrict__ x,
                   const float* __restrict__ wq,
                   const float* __restrict__ wk,
                   const float* __restrict__ wv)
{
    const int bn = blockIdx.x;
    const int m0 = blockIdx.y * 128;
    const float* Bp; float* C; int ldb;
    if (bn < 32)      { Bp = wq + bn * 128;        C = g_q + bn * 128;        ldb = NH  * HDIM; }
    else if (bn < 40) { Bp = wk + (bn - 32) * 128; C = g_k + (bn - 32) * 128; ldb = NKV * HDIM; }
    else              { Bp = wv + (bn - 40) * 128; C = g_v + (bn - 40) * 128; ldb = NKV * HDIM; }
    tc_gemm_body(x + (size_t)m0 * DIMX, Bp, C + (size_t)m0 * ldb, ldb, ldb);
}

__global__ __launch_bounds__(256, 1)
void out_tc_kernel(const float* __restrict__ wo, float* __restrict__ out)
{
    const int n0 = blockIdx.x * 128;
    const int m0 = blockIdx.y * 128;
    tc_gemm_body(g_ao + (size_t)m0 * DIMX, wo + n0,
                 out + (size_t)m0 * DIMX + n0, DIMX, DIMX);
}

// ---------------------------------------------------------------------------
// RoPE (interleaved pairs), in place on g_q / g_k
// ---------------------------------------------------------------------------
__global__ void rope_kernel(const float* __restrict__ cosb,
                            const float* __restrict__ sinb)
{
    int idx = blockIdx.x * blockDim.x + threadIdx.x;
    const int total = NT * (NH + NKV) * (HDIM / 2);
    if (idx >= total) return;
    int m    = idx & 63;
    int rest = idx >> 6;
    int head = rest % (NH + NKV);
    int t    = rest / (NH + NKV);
    float c = cosb[t * 64 + m];
    float s = sinb[t * 64 + m];
    float* base;
    if (head < NH) base = g_q + ((size_t)t * NH + head) * HDIM;
    else           base = g_k + ((size_t)t * NKV + (head - NH)) * HDIM;
    float t0 = base[2 * m];
    float t1 = base[2 * m + 1];
    base[2 * m]     = t0 * c - t1 * s;
    base[2 * m + 1] = t0 * s + t1 * c;
}

// ---------------------------------------------------------------------------
// Flash attention, sliding window, GQA (fp32 FFMA)
// ---------------------------------------------------------------------------
#define BQ 64
#define KPAD 132
#define PPAD 68
#define ATTN_SMEM ((3 * 64 * KPAD + 64 * PPAD) * 4)

__global__ __launch_bounds__(256, 1)
void attn_kernel()
{
    extern __shared__ float sm[];
    float* Qs = sm;
    float* Ks = Qs + 64 * KPAD;
    float* Vs = Ks + 64 * KPAD;
    float* Ps = Vs + 64 * KPAD;

    const int q0  = blockIdx.x * BQ;
    const int h   = blockIdx.y;
    const int b   = blockIdx.z;
    const int kvh = h >> 2;
    const int tid = threadIdx.x;
    const int ty  = tid >> 4;
    const int tx  = tid & 15;

    const float scale = 0.08838834764831845f;

    const float* qbase = g_q + ((size_t)(b * SEQ + q0) * NH + h) * HDIM;
#pragma unroll
    for (int it = 0; it < 8; it++) {
        int i = tid + it * 256;
        int r = i >> 5;
        int c4 = (i & 31) << 2;
        float4 v = *reinterpret_cast<const float4*>(qbase + (size_t)r * (NH * HDIM) + c4);
        v.x *= scale; v.y *= scale; v.z *= scale; v.w *= scale;
        *reinterpret_cast<float4*>(&Qs[r * KPAD + c4]) = v;
    }

    float m_run[4], l_run[4], o[4][8];
#pragma unroll
    for (int ii = 0; ii < 4; ii++) {
        m_run[ii] = -INFINITY;
        l_run[ii] = 0.0f;
#pragma unroll
        for (int cc = 0; cc < 8; cc++) o[ii][cc] = 0.0f;
    }

    int jlo = q0 - (WIN - 1);
    if (jlo < 0) jlo = 0;
    const int tk0 = jlo >> 6;
    const int tk1 = q0 >> 6;

    const float* kbase = g_k + ((size_t)(b * SEQ) * NKV + kvh) * HDIM;
    const float* vbase = g_v + ((size_t)(b * SEQ) * NKV + kvh) * HDIM;

    for (int tk = tk0; tk <= tk1; tk++) {
        const int j0 = tk * 64;
        __syncthreads();

#pragma unroll
        for (int it = 0; it < 8; it++) {
            int i = tid + it * 256;
            int r = i >> 5;
            int c4 = (i & 31) << 2;
            size_t goff = (size_t)(j0 + r) * (NKV * HDIM) + c4;
            *reinterpret_cast<float4*>(&Ks[r * KPAD + c4]) =
                *reinterpret_cast<const float4*>(kbase + goff);
            *reinterpret_cast<float4*>(&Vs[r * KPAD + c4]) =
                *reinterpret_cast<const float4*>(vbase + goff);
        }
        __syncthreads();

        float s[4][4];
#pragma unroll
        for (int ii = 0; ii < 4; ii++)
#pragma unroll
            for (int jj = 0; jj < 4; jj++) s[ii][jj] = 0.0f;

#pragma unroll 4
        for (int d4 = 0; d4 < 32; d4++) {
            float4 qv[4], kv[4];
#pragma unroll
            for (int ii = 0; ii < 4; ii++)
                qv[ii] = *reinterpret_cast<float4*>(&Qs[(ty * 4 + ii) * KPAD + d4 * 4]);
#pragma unroll
            for (int jj = 0; jj < 4; jj++)
                kv[jj] = *reinterpret_cast<float4*>(&Ks[(tx + 16 * jj) * KPAD + d4 * 4]);
#pragma unroll
            for (int ii = 0; ii < 4; ii++)
#pragma unroll
                for (int jj = 0; jj < 4; jj++) {
                    s[ii][jj] = fmaf(qv[ii].x, kv[jj].x, s[ii][jj]);
                    s[ii][jj] = fmaf(qv[ii].y, kv[jj].y, s[ii][jj]);
                    s[ii][jj] = fmaf(qv[ii].z, kv[jj].z, s[ii][jj]);
                    s[ii][jj] = fmaf(qv[ii].w, kv[jj].w, s[ii][jj]);
                }
        }

#pragma unroll
        for (int ii = 0; ii < 4; ii++) {
            const int qi = q0 + ty * 4 + ii;
            float mx = -INFINITY;
            bool valid[4];
#pragma unroll
            for (int jj = 0; jj < 4; jj++) {
                const int kj = j0 + tx + 16 * jj;
                bool ok = (kj <= qi) && (qi - kj < WIN);
                valid[jj] = ok;
                if (ok) mx = fmaxf(mx, s[ii][jj]);
            }
#pragma unroll
            for (int off = 8; off >= 1; off >>= 1)
                mx = fmaxf(mx, __shfl_xor_sync(0xffffffffu, mx, off, 32));

            float mnew = fmaxf(m_run[ii], mx);
            float alpha = __expf(m_run[ii] - mnew);
            if (mnew == -INFINITY) alpha = 1.0f;

            float rsum = 0.0f;
#pragma unroll
            for (int jj = 0; jj < 4; jj++) {
                float p = valid[jj] ? __expf(s[ii][jj] - mnew) : 0.0f;
                Ps[(ty * 4 + ii) * PPAD + tx + 16 * jj] = p;
                rsum += p;
            }
#pragma unroll
            for (int off = 8; off >= 1; off >>= 1)
                rsum += __shfl_xor_sync(0xffffffffu, rsum, off, 32);

            l_run[ii] = l_run[ii] * alpha + rsum;
            m_run[ii] = mnew;
#pragma unroll
            for (int cc = 0; cc < 8; cc++) o[ii][cc] *= alpha;
        }
        __syncthreads();

#pragma unroll 2
        for (int j4 = 0; j4 < 16; j4++) {
            float pr[4][4];
#pragma unroll
            for (int ii = 0; ii < 4; ii++)
                *reinterpret_cast<float4*>(pr[ii]) =
                    *reinterpret_cast<float4*>(&Ps[(ty * 4 + ii) * PPAD + j4 * 4]);
#pragma unroll
            for (int jj = 0; jj < 4; jj++) {
                const int j = j4 * 4 + jj;
                float4 v0 = *reinterpret_cast<float4*>(&Vs[j * KPAD + tx * 8]);
                float4 v1 = *reinterpret_cast<float4*>(&Vs[j * KPAD + tx * 8 + 4]);
#pragma unroll
                for (int ii = 0; ii < 4; ii++) {
                    float p = pr[ii][jj];
                    o[ii][0] = fmaf(p, v0.x, o[ii][0]);
                    o[ii][1] = fmaf(p, v0.y, o[ii][1]);
                    o[ii][2] = fmaf(p, v0.z, o[ii][2]);
                    o[ii][3] = fmaf(p, v0.w, o[ii][3]);
                    o[ii][4] = fmaf(p, v1.x, o[ii][4]);
                    o[ii][5] = fmaf(p, v1.y, o[ii][5]);
                    o[ii][6] = fmaf(p, v1.z, o[ii][6]);
                    o[ii][7] = fmaf(p, v1.w, o[ii][7]);
                }
            }
        }
    }

    float* obase = g_ao + (size_t)(b * SEQ + q0) * (NH * HDIM) + h * HDIM;
#pragma unroll
    for (int ii = 0; ii < 4; ii++) {
        float inv = 1.0f / l_run[ii];
        float4 v0 = make_float4(o[ii][0] * inv, o[ii][1] * inv, o[ii][2] * inv, o[ii][3] * inv);
        float4 v1 = make_float4(o[ii][4] * inv, o[ii][5] * inv, o[ii][6] * inv, o[ii][7] * inv);
        float* cp = obase + (size_t)(ty * 4 + ii) * (NH * HDIM) + tx * 8;
        *reinterpret_cast<float4*>(cp)     = v0;
        *reinterpret_cast<float4*>(cp + 4) = v1;
    }
}

// ---------------------------------------------------------------------------
extern "C" void kernel_launch(void* const* d_in, const int* in_sizes, int n_in,
                              void* d_out, int out_size)
{
    const float* x    = (const float*)d_in[0];
    const float* cosb = (const float*)d_in[1];
    const float* sinb = (const float*)d_in[2];
    const float* wq   = (const float*)d_in[3];
    const float* wk   = (const float*)d_in[4];
    const float* wv   = (const float*)d_in[5];
    const float* wo   = (const float*)d_in[6];
    float* out = (float*)d_out;

    cudaFuncSetAttribute(attn_kernel,
                         cudaFuncAttributeMaxDynamicSharedMemorySize, ATTN_SMEM);
    cudaFuncSetAttribute(qkv_tc_kernel,
                         cudaFuncAttributeMaxDynamicSharedMemorySize, GEMM_SMEM);
    cudaFuncSetAttribute(out_tc_kernel,
                         cudaFuncAttributeMaxDynamicSharedMemorySize, GEMM_SMEM);

    // 1. QKV projections (mma.sync tf32, fused grid)
    qkv_tc_kernel<<<dim3(48, 32), 256, GEMM_SMEM>>>(x, wq, wk, wv);

    // 2. RoPE
    {
        const int total = NT * (NH + NKV) * (HDIM / 2);
        rope_kernel<<<(total + 255) / 256, 256>>>(cosb, sinb);
    }

    // 3. Sliding-window GQA attention
    attn_kernel<<<dim3(SEQ / BQ, NH, BB), 256, ATTN_SMEM>>>();

    // 4. Output projection (mma.sync tf32)
    out_tc_kernel<<<dim3(32, 32), 256, GEMM_SMEM>>>(wo, out);
}

// round 10
// speedup vs baseline: 3.9419x; 1.5090x over previous
#include <cuda_runtime.h>
#include <math.h>
#include <stdint.h>

#define DIMX  4096
#define NT    4096
#define NH    32
#define NKV   8
#define HDIM  128
#define BB    2
#define SEQ   2048
#define WIN   1024
#define ATT_SCALE 0.08838834764831845f

// ---------------------------------------------------------------------------
// Scratch (device globals)
// ---------------------------------------------------------------------------
__device__ float g_q  [(size_t)NT * NH  * HDIM];
__device__ float g_k  [(size_t)NT * NKV * HDIM];
__device__ float g_v  [(size_t)NT * NKV * HDIM];
__device__ float g_ao [(size_t)NT * NH  * HDIM];

// packed bf16x2 planes: word m = elements (2m, 2m+1); low 16 bits = even elem
__device__ __align__(16) uint32_t g_qhi[(size_t)NT * NH  * 64];
__device__ __align__(16) uint32_t g_qlo[(size_t)NT * NH  * 64];
__device__ __align__(16) uint32_t g_khi[(size_t)NT * NKV * 64];
__device__ __align__(16) uint32_t g_klo[(size_t)NT * NKV * 64];
__device__ __align__(16) uint32_t g_vthi[(size_t)BB * NKV * HDIM * (SEQ / 2)];
__device__ __align__(16) uint32_t g_vtlo[(size_t)BB * NKV * HDIM * (SEQ / 2)];

// ---------------------------------------------------------------------------
// PTX helpers (sm_80-compatible subset)
// ---------------------------------------------------------------------------
#define CP_ASYNC16(dst, src) \
    asm volatile("cp.async.cg.shared.global [%0], [%1], 16;" :: "r"(dst), "l"(src))
#define CP_COMMIT() asm volatile("cp.async.commit_group;" ::: "memory")
#define CP_WAIT(n)  asm volatile("cp.async.wait_group %0;" :: "n"(n) : "memory")

__device__ __forceinline__ uint32_t smem_u32(const void* p) {
    uint32_t a;
    asm("{ .reg .u64 t; cvta.to.shared.u64 t, %1; cvt.u32.u64 %0, t; }" : "=r"(a) : "l"(p));
    return a;
}
__device__ __forceinline__ uint32_t tf32u(float x) {
    uint32_t u;
    asm("cvt.rn.tf32.f32 %0, %1;" : "=r"(u) : "f"(x));
    return u;
}
__device__ __forceinline__ void mma_tf32(float* acc, const uint32_t* a, const uint32_t* b)
{
    asm volatile(
        "mma.sync.aligned.m16n8k8.row.col.f32.tf32.tf32.f32 "
        "{%0,%1,%2,%3}, {%4,%5,%6,%7}, {%8,%9}, {%0,%1,%2,%3};"
        : "+f"(acc[0]), "+f"(acc[1]), "+f"(acc[2]), "+f"(acc[3])
        : "r"(a[0]), "r"(a[1]), "r"(a[2]), "r"(a[3]), "r"(b[0]), "r"(b[1]));
}
__device__ __forceinline__ void mma_bf16(float* c, const uint32_t* a, uint32_t b0, uint32_t b1)
{
    asm volatile(
        "mma.sync.aligned.m16n8k16.row.col.f32.bf16.bf16.f32 "
        "{%0,%1,%2,%3}, {%4,%5,%6,%7}, {%8,%9}, {%0,%1,%2,%3};"
        : "+f"(c[0]), "+f"(c[1]), "+f"(c[2]), "+f"(c[3])
        : "r"(a[0]), "r"(a[1]), "r"(a[2]), "r"(a[3]), "r"(b0), "r"(b1));
}
// hi = truncate-to-bf16 pair (exact residual); lo = RN-bf16 of residual
__device__ __forceinline__ void split_pair(float o0, float o1, uint32_t& hi, uint32_t& lo)
{
    uint32_t u0 = __float_as_uint(o0), u1 = __float_as_uint(o1);
    hi = __byte_perm(u0, u1, 0x7632);
    float l0 = o0 - __uint_as_float(u0 & 0xffff0000u);
    float l1 = o1 - __uint_as_float(u1 & 0xffff0000u);
    asm("cvt.rn.bf16x2.f32 %0, %1, %2;" : "=r"(lo) : "f"(l1), "f"(l0));
}

// ---------------------------------------------------------------------------
// Tensor-core tf32 GEMM (unchanged from round 7 — known good)
// ---------------------------------------------------------------------------
#define BK    32
#define AST   36
#define BST   136
#define NSTG  3
#define AS_FLOATS (128 * AST)
#define BS_FLOATS (BK * BST)
#define GEMM_SMEM ((NSTG * (AS_FLOATS + BS_FLOATS)) * 4)
#define NITER (DIMX / BK)

__device__ __forceinline__ void g_load_stage(
    uint32_t sa, uint32_t sb,
    const float* __restrict__ A, const float* __restrict__ B,
    int ldb, int kt, int tid)
{
    const float* ab = A + kt;
#pragma unroll
    for (int j = 0; j < 4; j++) {
        int c = tid + j * 256;
        int r = c >> 3, w = c & 7;
        CP_ASYNC16(sa + (uint32_t)(r * AST + w * 4) * 4, ab + (size_t)r * DIMX + w * 4);
    }
    const float* bb = B + (size_t)kt * ldb;
#pragma unroll
    for (int j = 0; j < 4; j++) {
        int c = tid + j * 256;
        int r = c >> 5, w = c & 31;
        CP_ASYNC16(sb + (uint32_t)(r * BST + w * 4) * 4, bb + (size_t)r * ldb + w * 4);
    }
}

__device__ __forceinline__ void tc_gemm_body(
    const float* __restrict__ A, const float* __restrict__ B,
    float* __restrict__ C, int ldb, int ldc)
{
    extern __shared__ float sh[];
    float* As = sh;
    float* Bs = sh + NSTG * AS_FLOATS;
    const uint32_t sa0 = smem_u32(As);
    const uint32_t sb0 = smem_u32(Bs);

    const int tid  = threadIdx.x;
    const int wid  = tid >> 5;
    const int lane = tid & 31;
    const int wm   = (wid >> 2) * 64;
    const int wn   = (wid & 3) * 32;
    const int gid  = lane >> 2;
    const int tig  = lane & 3;

    float acc[4][4][4];
#pragma unroll
    for (int mt = 0; mt < 4; mt++)
#pragma unroll
        for (int nt = 0; nt < 4; nt++)
#pragma unroll
            for (int q = 0; q < 4; q++) acc[mt][nt][q] = 0.0f;

#pragma unroll
    for (int p = 0; p < NSTG - 1; p++) {
        g_load_stage(sa0 + (uint32_t)p * AS_FLOATS * 4, sb0 + (uint32_t)p * BS_FLOATS * 4,
                     A, B, ldb, p * BK, tid);
        CP_COMMIT();
    }

    for (int i = 0; i < NITER; i++) {
        CP_WAIT(NSTG - 2);
        __syncthreads();
        const int s = i % NSTG;
        const float* Asb = As + s * AS_FLOATS + wm * AST;
        const float* Bsb = Bs + s * BS_FLOATS + wn;

#pragma unroll
        for (int ks = 0; ks < 4; ks++) {
            const int k0 = ks * 8;
            uint32_t af[4][4], bf[4][2];
#pragma unroll
            for (int mt = 0; mt < 4; mt++) {
                const float* ap = Asb + (mt * 16 + gid) * AST + k0 + tig;
                af[mt][0] = tf32u(ap[0]);
                af[mt][1] = tf32u(ap[8 * AST]);
                af[mt][2] = tf32u(ap[4]);
                af[mt][3] = tf32u(ap[8 * AST + 4]);
            }
#pragma unroll
            for (int nt = 0; nt < 4; nt++) {
                const float* bp = Bsb + (k0 + tig) * BST + nt * 8 + gid;
                bf[nt][0] = tf32u(bp[0]);
                bf[nt][1] = tf32u(bp[4 * BST]);
            }
#pragma unroll
            for (int mt = 0; mt < 4; mt++)
#pragma unroll
                for (int nt = 0; nt < 4; nt++)
                    mma_tf32(acc[mt][nt], af[mt], bf[nt]);
        }

        const int ip = i + NSTG - 1;
        if (ip < NITER) {
            const int sp = ip % NSTG;
            g_load_stage(sa0 + (uint32_t)sp * AS_FLOATS * 4, sb0 + (uint32_t)sp * BS_FLOATS * 4,
                         A, B, ldb, ip * BK, tid);
        }
        CP_COMMIT();
    }

#pragma unroll
    for (int mt = 0; mt < 4; mt++) {
#pragma unroll
        for (int nt = 0; nt < 4; nt++) {
            const int r0 = wm + mt * 16 + gid;
            const int cc = wn + nt * 8 + tig * 2;
            *reinterpret_cast<float2*>(C + (size_t)r0 * ldc + cc) =
                make_float2(acc[mt][nt][0], acc[mt][nt][1]);
            *reinterpret_cast<float2*>(C + (size_t)(r0 + 8) * ldc + cc) =
                make_float2(acc[mt][nt][2], acc[mt][nt][3]);
        }
    }
}

__global__ __launch_bounds__(256, 1)
void qkv_tc_kernel(const float* __restrict__ x, const float* __restrict__ wq,
                   const float* __restrict__ wk, const float* __restrict__ wv)
{
    const int bn = blockIdx.x;
    const int m0 = blockIdx.y * 128;
    const float* Bp; float* C; int ldb;
    if (bn < 32)      { Bp = wq + bn * 128;        C = g_q + bn * 128;        ldb = NH  * HDIM; }
    else if (bn < 40) { Bp = wk + (bn - 32) * 128; C = g_k + (bn - 32) * 128; ldb = NKV * HDIM; }
    else              { Bp = wv + (bn - 40) * 128; C = g_v + (bn - 40) * 128; ldb = NKV * HDIM; }
    tc_gemm_body(x + (size_t)m0 * DIMX, Bp, C + (size_t)m0 * ldb, ldb, ldb);
}

__global__ __launch_bounds__(256, 1)
void out_tc_kernel(const float* __restrict__ wo, float* __restrict__ out)
{
    const int n0 = blockIdx.x * 128;
    const int m0 = blockIdx.y * 128;
    tc_gemm_body(g_ao + (size_t)m0 * DIMX, wo + n0, out + (size_t)m0 * DIMX + n0, DIMX, DIMX);
}

// ---------------------------------------------------------------------------
// RoPE: read fp32 g_q/g_k, write packed bf16 hi/lo planes (Q pre-scaled)
// ---------------------------------------------------------------------------
__global__ void rope_kernel(const float* __restrict__ cosb, const float* __restrict__ sinb)
{
    int idx = blockIdx.x * blockDim.x + threadIdx.x;
    const int total = NT * (NH + NKV) * 64;
    if (idx >= total) return;
    int m    = idx & 63;
    int rest = idx >> 6;
    int head = rest % (NH + NKV);
    int t    = rest / (NH + NKV);
    float c = cosb[t * 64 + m];
    float s = sinb[t * 64 + m];
    uint32_t hi, lo;
    if (head < NH) {
        const float* base = g_q + ((size_t)t * NH + head) * HDIM;
        float t0 = base[2 * m], t1 = base[2 * m + 1];
        split_pair((t0 * c - t1 * s) * ATT_SCALE, (t0 * s + t1 * c) * ATT_SCALE, hi, lo);
        size_t w = ((size_t)t * NH + head) * 64 + m;
        g_qhi[w] = hi; g_qlo[w] = lo;
    } else {
        int kv = head - NH;
        const float* base = g_k + ((size_t)t * NKV + kv) * HDIM;
        float t0 = base[2 * m], t1 = base[2 * m + 1];
        split_pair(t0 * c - t1 * s, t0 * s + t1 * c, hi, lo);
        size_t w = ((size_t)t * NKV + kv) * 64 + m;
        g_khi[w] = hi; g_klo[w] = lo;
    }
}

// ---------------------------------------------------------------------------
// V split+transpose: g_v [t][kv][128] -> g_vt{hi,lo} [(b*NKV+kv)][d][key-pair]
// ---------------------------------------------------------------------------
__global__ void vsplit_kernel()
{
    __shared__ float smv[64 * 129];
    const int j0 = blockIdx.x * 64, kv = blockIdx.y, b = blockIdx.z;
    const int tid = threadIdx.x;
#pragma unroll
    for (int it = 0; it < 32; it++) {
        int i = tid + it * 256;
        int r = i >> 7, d = i & 127;
        smv[r * 129 + d] = g_v[((size_t)(b * SEQ + j0 + r) * NKV + kv) * HDIM + d];
    }
    __syncthreads();
    const size_t ob = (size_t)(b * NKV + kv) * HDIM * (SEQ / 2) + (j0 >> 1);
#pragma unroll
    for (int it = 0; it < 16; it++) {
        int i = tid + it * 256;
        int d = i >> 5, j = i & 31;
        uint32_t hi, lo;
        split_pair(smv[(2 * j) * 129 + d], smv[(2 * j + 1) * 129 + d], hi, lo);
        g_vthi[ob + (size_t)d * (SEQ / 2) + j] = hi;
        g_vtlo[ob + (size_t)d * (SEQ / 2) + j] = lo;
    }
}

// ---------------------------------------------------------------------------
// Flash attention: bf16x3 mma.sync, sliding window, GQA.
// CTA: 128 q-rows x 64-key tiles, 8 warps (16 rows each), 2-stage cp.async.
// ---------------------------------------------------------------------------
#define ATW 68
#define VTW 36
#define QPLANE (128 * ATW)                       // 8704 words
#define KPLANE (64 * ATW)                        // 4352
#define VPLANE (128 * VTW)                       // 4608
#define STG_WORDS (2 * KPLANE + 2 * VPLANE)      // 17920
#define ATTN_SMEM ((2 * QPLANE + 2 * STG_WORDS) * 4)   // 212992 B

__device__ __forceinline__ void attn_load_stage(uint32_t stb, int b, int kv, int j0, int tid)
{
    const size_t kbase = ((size_t)(b * SEQ + j0) * NKV + kv) * 64;
#pragma unroll
    for (int it = 0; it < 4; it++) {
        int i = tid + it * 256;
        int r = i >> 4, c = i & 15;
        size_t src = kbase + (size_t)r * (NKV * 64) + c * 4;
        CP_ASYNC16(stb + (uint32_t)(r * ATW + c * 4) * 4, g_khi + src);
        CP_ASYNC16(stb + (uint32_t)(KPLANE + r * ATW + c * 4) * 4, g_klo + src);
    }
    const size_t vbase = (size_t)(b * NKV + kv) * HDIM * (SEQ / 2) + (j0 >> 1);
#pragma unroll
    for (int it = 0; it < 4; it++) {
        int i = tid + it * 256;
        int r = i >> 3, c = i & 7;
        size_t src = vbase + (size_t)r * (SEQ / 2) + c * 4;
        CP_ASYNC16(stb + (uint32_t)(2 * KPLANE + r * VTW + c * 4) * 4, g_vthi + src);
        CP_ASYNC16(stb + (uint32_t)(2 * KPLANE + VPLANE + r * VTW + c * 4) * 4, g_vtlo + src);
    }
}

__global__ __launch_bounds__(256, 1)
void attn_kernel()
{
    extern __shared__ uint32_t sw[];
    const int q0 = blockIdx.x * 128;
    const int h = blockIdx.y, b = blockIdx.z, kv = h >> 2;
    const int tid = threadIdx.x, wid = tid >> 5, lane = tid & 31;
    const int gid = lane >> 2, tig = lane & 3;
    const int qb = wid * 16;
    const uint32_t sbase = smem_u32(sw);

    // Q planes -> smem (once)
    {
        const uint4* qh = reinterpret_cast<const uint4*>(g_qhi + ((size_t)(b * SEQ + q0) * NH + h) * 64);
        const uint4* ql = reinterpret_cast<const uint4*>(g_qlo + ((size_t)(b * SEQ + q0) * NH + h) * 64);
#pragma unroll
        for (int it = 0; it < 8; it++) {
            int i = tid + it * 256;
            int r = i >> 4, c = i & 15;
            *reinterpret_cast<uint4*>(sw + r * ATW + c * 4)          = qh[(size_t)r * (NH * 16) + c];
            *reinterpret_cast<uint4*>(sw + QPLANE + r * ATW + c * 4) = ql[(size_t)r * (NH * 16) + c];
        }
    }

    float oacc[16][4];
#pragma unroll
    for (int n = 0; n < 16; n++)
        oacc[n][0] = oacc[n][1] = oacc[n][2] = oacc[n][3] = 0.0f;
    float mr0 = -1e30f, mr1 = -1e30f, lr0 = 0.0f, lr1 = 0.0f;

    int jlo = q0 - (WIN - 1); if (jlo < 0) jlo = 0;
    const int tk0 = jlo >> 6, tk1 = (q0 + 127) >> 6;

    const uint32_t stb0 = sbase + (uint32_t)(2 * QPLANE) * 4;
    attn_load_stage(stb0, b, kv, tk0 * 64, tid);
    CP_COMMIT();

    const int r0 = q0 + qb + gid, r1 = r0 + 8;
    int s = 0;
    for (int tk = tk0; tk <= tk1; tk++, s ^= 1) {
        const int j0 = tk * 64;
        __syncthreads();                 // all warps done with buffer s^1
        if (tk < tk1) attn_load_stage(stb0 + (uint32_t)((s ^ 1) * STG_WORDS) * 4, b, kv, j0 + 64, tid);
        CP_COMMIT();
        CP_WAIT(1);                      // stage s complete
        __syncthreads();

        const bool active = (j0 <= q0 + qb + 15) && ((q0 + qb) - (j0 + 63) < WIN);
        if (active) {
            const uint32_t* KH = sw + 2 * QPLANE + s * STG_WORDS;
            const uint32_t* KL = KH + KPLANE;
            const uint32_t* VH = KL + KPLANE;
            const uint32_t* VL = VH + VPLANE;

            float sacc[8][4];
#pragma unroll
            for (int n = 0; n < 8; n++)
                sacc[n][0] = sacc[n][1] = sacc[n][2] = sacc[n][3] = 0.0f;

            // QK: 8 k16-steps x 8 n-tiles x 3 mma
#pragma unroll
            for (int kt = 0; kt < 8; kt++) {
                uint32_t ah[4], alr[4];
                const int ab = (qb + gid) * ATW + kt * 8 + tig;
                ah[0]  = sw[ab];               ah[1]  = sw[ab + 8 * ATW];
                ah[2]  = sw[ab + 4];           ah[3]  = sw[ab + 8 * ATW + 4];
                alr[0] = sw[QPLANE + ab];      alr[1] = sw[QPLANE + ab + 8 * ATW];
                alr[2] = sw[QPLANE + ab + 4];  alr[3] = sw[QPLANE + ab + 8 * ATW + 4];
#pragma unroll
                for (int nt = 0; nt < 8; nt++) {
                    const int bb2 = (nt * 8 + gid) * ATW + kt * 8 + tig;
                    uint32_t bh0 = KH[bb2], bh1 = KH[bb2 + 4];
                    uint32_t bl0 = KL[bb2], bl1 = KL[bb2 + 4];
                    mma_bf16(sacc[nt], ah, bh0, bh1);
                    mma_bf16(sacc[nt], ah, bl0, bl1);
                    mma_bf16(sacc[nt], alr, bh0, bh1);
                }
            }

            // mask + online softmax (rows r0, r1 live in this thread-quad)
            float mx0 = -3e38f, mx1 = -3e38f;
#pragma unroll
            for (int nt = 0; nt < 8; nt++) {
                const int cb = j0 + nt * 8 + 2 * tig;
#pragma unroll
                for (int e = 0; e < 2; e++) {
                    const int col = cb + e;
                    if (col > r0 || r0 - col >= WIN) sacc[nt][e]     = -3e38f;
                    if (col > r1 || r1 - col >= WIN) sacc[nt][2 + e] = -3e38f;
                    mx0 = fmaxf(mx0, sacc[nt][e]);
                    mx1 = fmaxf(mx1, sacc[nt][2 + e]);
                }
            }
            mx0 = fmaxf(mx0, __shfl_xor_sync(0xffffffffu, mx0, 1));
            mx0 = fmaxf(mx0, __shfl_xor_sync(0xffffffffu, mx0, 2));
            mx1 = fmaxf(mx1, __shfl_xor_sync(0xffffffffu, mx1, 1));
            mx1 = fmaxf(mx1, __shfl_xor_sync(0xffffffffu, mx1, 2));

            const float mn0 = fmaxf(mr0, mx0), mn1 = fmaxf(mr1, mx1);
            const float a0 = __expf(mr0 - mn0), a1 = __expf(mr1 - mn1);
            float rs0 = 0.0f, rs1 = 0.0f;
#pragma unroll
            for (int nt = 0; nt < 8; nt++) {
#pragma unroll
                for (int e = 0; e < 2; e++) {
                    float p0 = __expf(sacc[nt][e] - mn0);
                    float p1 = __expf(sacc[nt][2 + e] - mn1);
                    sacc[nt][e] = p0; sacc[nt][2 + e] = p1;
                    rs0 += p0; rs1 += p1;
                }
            }
            rs0 += __shfl_xor_sync(0xffffffffu, rs0, 1);
            rs0 += __shfl_xor_sync(0xffffffffu, rs0, 2);
            rs1 += __shfl_xor_sync(0xffffffffu, rs1, 1);
            rs1 += __shfl_xor_sync(0xffffffffu, rs1, 2);
            lr0 = lr0 * a0 + rs0; lr1 = lr1 * a1 + rs1;
            mr0 = mn0; mr1 = mn1;
#pragma unroll
            for (int n = 0; n < 16; n++) {
                oacc[n][0] *= a0; oacc[n][1] *= a0;
                oacc[n][2] *= a1; oacc[n][3] *= a1;
            }

            // PV: P fragments built in-register from QK accumulators
#pragma unroll
            for (int kt2 = 0; kt2 < 4; kt2++) {
                uint32_t ph[4], pl[4];
                split_pair(sacc[2 * kt2][0],     sacc[2 * kt2][1],     ph[0], pl[0]);
                split_pair(sacc[2 * kt2][2],     sacc[2 * kt2][3],     ph[1], pl[1]);
                split_pair(sacc[2 * kt2 + 1][0], sacc[2 * kt2 + 1][1], ph[2], pl[2]);
                split_pair(sacc[2 * kt2 + 1][2], sacc[2 * kt2 + 1][3], ph[3], pl[3]);
#pragma unroll
                for (int nt2 = 0; nt2 < 16; nt2++) {
                    const int vb = (nt2 * 8 + gid) * VTW + kt2 * 8 + tig;
                    uint32_t vh0 = VH[vb], vh1 = VH[vb + 4];
                    uint32_t vl0 = VL[vb], vl1 = VL[vb + 4];
                    mma_bf16(oacc[nt2], ph, vh0, vh1);
                    mma_bf16(oacc[nt2], ph, vl0, vl1);
                    mma_bf16(oacc[nt2], pl, vh0, vh1);
                }
            }
        }
    }

    // epilogue: normalize, store fp32 rows r0 / r1
    const float i0 = 1.0f / lr0, i1 = 1.0f / lr1;
    float* ob0 = g_ao + (size_t)(b * SEQ + q0 + qb + gid) * (NH * HDIM) + h * HDIM;
    float* ob1 = ob0 + (size_t)8 * (NH * HDIM);
#pragma unroll
    for (int nt2 = 0; nt2 < 16; nt2++) {
        const int d = nt2 * 8 + 2 * tig;
        *reinterpret_cast<float2*>(ob0 + d) = make_float2(oacc[nt2][0] * i0, oacc[nt2][1] * i0);
        *reinterpret_cast<float2*>(ob1 + d) = make_float2(oacc[nt2][2] * i1, oacc[nt2][3] * i1);
    }
}

// ---------------------------------------------------------------------------
extern "C" void kernel_launch(void* const* d_in, const int* in_sizes, int n_in,
                              void* d_out, int out_size)
{
    const float* x    = (const float*)d_in[0];
    const float* cosb = (const float*)d_in[1];
    const float* sinb = (const float*)d_in[2];
    const float* wq   = (const float*)d_in[3];
    const float* wk   = (const float*)d_in[4];
    const float* wv   = (const float*)d_in[5];
    const float* wo   = (const float*)d_in[6];
    float* out = (float*)d_out;

    cudaFuncSetAttribute(qkv_tc_kernel, cudaFuncAttributeMaxDynamicSharedMemorySize, GEMM_SMEM);
    cudaFuncSetAttribute(out_tc_kernel, cudaFuncAttributeMaxDynamicSharedMemorySize, GEMM_SMEM);
    cudaFuncSetAttribute(attn_kernel,   cudaFuncAttributeMaxDynamicSharedMemorySize, ATTN_SMEM);

    // 1. QKV projections (mma.sync tf32)
    qkv_tc_kernel<<<dim3(48, 32), 256, GEMM_SMEM>>>(x, wq, wk, wv);

    // 2. RoPE -> bf16 hi/lo planes; V split+transpose
    {
        const int total = NT * (NH + NKV) * 64;
        rope_kernel<<<(total + 255) / 256, 256>>>(cosb, sinb);
        vsplit_kernel<<<dim3(SEQ / 64, NKV, BB), 256>>>();
    }

    // 3. Sliding-window GQA attention (bf16x3 mma.sync)
    attn_kernel<<<dim3(SEQ / 128, NH, BB), 256, ATTN_SMEM>>>();

    // 4. Output projection (mma.sync tf32)
    out_tc_kernel<<<dim3(32, 32), 256, GEMM_SMEM>>>(wo, out);
}